// round 1
// baseline (speedup 1.0000x reference)
#include <cuda_runtime.h>
#include <cuda_bf16.h>
#include <cstdint>
#include <cstddef>

// ---------------- problem constants (fixed shapes) ----------------
constexpr int kC  = 1024;   // model dim
constexpr int kE  = 8;      // experts
constexpr int kH  = 4096;   // expert hidden
constexpr int kN  = 8192;   // tokens (B*T)
constexpr int kBM = 128;
constexpr int kBN = 128;
constexpr int kBK = 16;
constexpr int kRMax = kN + kE * kBM;   // 9216 padded rows
constexpr int kNRT  = kRMax / kBM;     // 72 row tiles
constexpr int kSK   = kBK + 2;         // smem row stride (bf16 elems), pad vs bank conflicts

// ---------------- device scratch (static, allocation-free) ----------------
__device__ float g_xg[(size_t)kRMax * kC];        // gathered tokens (grouped by expert)
__device__ float g_h [(size_t)kRMax * kH];        // hidden activations
__device__ float g_prob[kN];
__device__ int   g_idx[kN];
__device__ int   g_perm[kRMax];
__device__ int   g_cnt[kE];
__device__ int   g_cur[kE];
__device__ int   g_poff[kE + 1];

// ---------------- small kernels ----------------
__global__ void reset_kernel() {
    int t = threadIdx.x;
    if (t < kE) { g_cnt[t] = 0; g_cur[t] = 0; }
}

__global__ void router_kernel(const float* __restrict__ x,
                              const float* __restrict__ Wr,
                              const float* __restrict__ br) {
    int tok  = (blockIdx.x * blockDim.x + threadIdx.x) >> 5;
    int lane = threadIdx.x & 31;
    if (tok >= kN) return;
    const float* xr = x + (size_t)tok * kC;
    float acc[kE];
#pragma unroll
    for (int e = 0; e < kE; e++) acc[e] = 0.f;
    for (int c = lane; c < kC; c += 32) {
        float xv = xr[c];
        const float4* w = (const float4*)(Wr + (size_t)c * kE);
        float4 w0 = w[0], w1 = w[1];
        acc[0] += xv * w0.x; acc[1] += xv * w0.y; acc[2] += xv * w0.z; acc[3] += xv * w0.w;
        acc[4] += xv * w1.x; acc[5] += xv * w1.y; acc[6] += xv * w1.z; acc[7] += xv * w1.w;
    }
#pragma unroll
    for (int e = 0; e < kE; e++)
        for (int o = 16; o > 0; o >>= 1)
            acc[e] += __shfl_xor_sync(0xffffffffu, acc[e], o);
    if (lane == 0) {
        float m = -1e30f; int bi = 0;
#pragma unroll
        for (int e = 0; e < kE; e++) {
            acc[e] += br[e];
            if (acc[e] > m) { m = acc[e]; bi = e; }   // first-max, matches argmax
        }
        float s = 0.f;
#pragma unroll
        for (int e = 0; e < kE; e++) s += expf(acc[e] - m);
        g_prob[tok] = 1.f / s;    // softmax max = exp(0)/sum
        g_idx[tok]  = bi;
        atomicAdd(&g_cnt[bi], 1);
    }
}

__global__ void offsets_kernel(float* aux_out) {
    if (threadIdx.x == 0) {
        int p = 0; float s = 0.f;
#pragma unroll
        for (int e = 0; e < kE; e++) {
            g_poff[e] = p;
            int c = g_cnt[e];
            p += (c + kBM - 1) / kBM * kBM;          // pad each expert to tile multiple
            float f = (float)c / (float)kN;
            float d = f - (1.0f / (float)kE);
            s += d * d;
        }
        g_poff[kE] = p;
        if (aux_out) *aux_out = s / (float)kE;
    }
}

__global__ void gather_kernel(const float* __restrict__ x) {
    int tok  = (blockIdx.x * blockDim.x + threadIdx.x) >> 5;
    int lane = threadIdx.x & 31;
    if (tok >= kN) return;
    int e = g_idx[tok];
    int pos = 0;
    if (lane == 0) pos = g_poff[e] + atomicAdd(&g_cur[e], 1);
    pos = __shfl_sync(0xffffffffu, pos, 0);
    if (lane == 0) g_perm[pos] = tok;
    const float4* src = (const float4*)(x + (size_t)tok * kC);
    float4* dst = (float4*)(g_xg + (size_t)pos * kC);
#pragma unroll
    for (int i = lane; i < kC / 4; i += 32) dst[i] = src[i];
}

// ---------------- GEMM core ----------------
__device__ __forceinline__ float geluf(float v) {
    return 0.5f * v * (1.0f + erff(v * 0.70710678118654752f));
}

__device__ __forceinline__ void mma16816(float* c, const uint32_t* a, const uint32_t* b) {
    asm volatile(
        "mma.sync.aligned.m16n8k16.row.col.f32.bf16.bf16.f32 "
        "{%0,%1,%2,%3}, {%4,%5,%6,%7}, {%8,%9}, {%0,%1,%2,%3};\n"
        : "+f"(c[0]), "+f"(c[1]), "+f"(c[2]), "+f"(c[3])
        : "r"(a[0]), "r"(a[1]), "r"(a[2]), "r"(a[3]), "r"(b[0]), "r"(b[1]));
}

// Grouped GEMM: D[R, LDB-cols] = act(A[R, KDIM] @ B_e[KDIM, LDB] + bias_e)
// SECOND=false: A=g_xg, D=g_h, act=gelu.  SECOND=true: A=g_h, D=out (scatter, x gate).
template <int KDIM, int LDA, int LDB, bool SECOND>
__global__ __launch_bounds__(256, 1)
void moe_gemm_kernel(const float* __restrict__ Ball,
                     const float* __restrict__ biasAll,
                     float* __restrict__ OutP) {
    __shared__ __nv_bfloat16 sAhi[kBM][kSK];
    __shared__ __nv_bfloat16 sAlo[kBM][kSK];
    __shared__ __nv_bfloat16 sBhi[kBN][kSK];
    __shared__ __nv_bfloat16 sBlo[kBN][kSK];

    const int row0 = blockIdx.y * kBM;
    if (row0 >= g_poff[kE]) return;
    int e = 0;
    while (e < kE - 1 && row0 >= g_poff[e + 1]) e++;

    const float* A    = SECOND ? (const float*)g_h : (const float*)g_xg;
    float*       Dout = SECOND ? OutP : (float*)g_h;

    const int tid  = threadIdx.x;
    const int warp = tid >> 5;
    const int lane = tid & 31;
    const int wm   = warp & 3;    // 4 row-blocks of 32
    const int wn   = warp >> 2;   // 2 col-blocks of 64

    const float* Bp    = Ball  + (size_t)e * KDIM * LDB + (size_t)blockIdx.x * kBN;
    const float* biasE = biasAll + (size_t)e * LDB + (size_t)blockIdx.x * kBN;

    const int arow = tid >> 1;
    const int ac0  = (tid & 1) * 8;
    const int bkr  = tid >> 4;
    const int bn0  = (tid & 15) * 8;

    const float* Aload = A  + (size_t)(row0 + arow) * LDA + ac0;
    const float* Bload = Bp + (size_t)bkr * LDB + bn0;

    float acc[2][8][4];
#pragma unroll
    for (int i = 0; i < 2; i++)
#pragma unroll
        for (int j = 0; j < 8; j++)
#pragma unroll
            for (int q = 0; q < 4; q++) acc[i][j][q] = 0.f;

    float4 aR0 = *(const float4*)(Aload);
    float4 aR1 = *(const float4*)(Aload + 4);
    float4 bR0 = *(const float4*)(Bload);
    float4 bR1 = *(const float4*)(Bload + 4);

    constexpr int KT = KDIM / kBK;
    for (int kt = 0; kt < KT; kt++) {
        {   // hi/lo split into smem
            float av[8] = {aR0.x, aR0.y, aR0.z, aR0.w, aR1.x, aR1.y, aR1.z, aR1.w};
#pragma unroll
            for (int q = 0; q < 8; q++) {
                __nv_bfloat16 hv = __float2bfloat16(av[q]);
                sAhi[arow][ac0 + q] = hv;
                sAlo[arow][ac0 + q] = __float2bfloat16(av[q] - __bfloat162float(hv));
            }
            float bv[8] = {bR0.x, bR0.y, bR0.z, bR0.w, bR1.x, bR1.y, bR1.z, bR1.w};
#pragma unroll
            for (int q = 0; q < 8; q++) {
                __nv_bfloat16 hv = __float2bfloat16(bv[q]);
                sBhi[bn0 + q][bkr] = hv;                 // transposed: [n][k]
                sBlo[bn0 + q][bkr] = __float2bfloat16(bv[q] - __bfloat162float(hv));
            }
        }
        __syncthreads();
        if (kt + 1 < KT) {   // prefetch next K-chunk
            const float* ap = Aload + (kt + 1) * kBK;
            aR0 = *(const float4*)ap;
            aR1 = *(const float4*)(ap + 4);
            const float* bp = Bload + (size_t)(kt + 1) * kBK * LDB;
            bR0 = *(const float4*)bp;
            bR1 = *(const float4*)(bp + 4);
        }
        // fragments
        uint32_t ahi[2][4], alo[2][4], bhi[8][2], blo[8][2];
        const int rb = wm * 32 + (lane >> 2);
        const int cf = (lane & 3) * 2;
#pragma unroll
        for (int i = 0; i < 2; i++) {
            int r = rb + i * 16;
            ahi[i][0] = *(const uint32_t*)&sAhi[r][cf];
            ahi[i][1] = *(const uint32_t*)&sAhi[r + 8][cf];
            ahi[i][2] = *(const uint32_t*)&sAhi[r][cf + 8];
            ahi[i][3] = *(const uint32_t*)&sAhi[r + 8][cf + 8];
            alo[i][0] = *(const uint32_t*)&sAlo[r][cf];
            alo[i][1] = *(const uint32_t*)&sAlo[r + 8][cf];
            alo[i][2] = *(const uint32_t*)&sAlo[r][cf + 8];
            alo[i][3] = *(const uint32_t*)&sAlo[r + 8][cf + 8];
        }
#pragma unroll
        for (int j = 0; j < 8; j++) {
            int nn = wn * 64 + j * 8 + (lane >> 2);
            bhi[j][0] = *(const uint32_t*)&sBhi[nn][cf];
            bhi[j][1] = *(const uint32_t*)&sBhi[nn][cf + 8];
            blo[j][0] = *(const uint32_t*)&sBlo[nn][cf];
            blo[j][1] = *(const uint32_t*)&sBlo[nn][cf + 8];
        }
#pragma unroll
        for (int i = 0; i < 2; i++)
#pragma unroll
            for (int j = 0; j < 8; j++) {
                mma16816(acc[i][j], ahi[i], bhi[j]);   // hi*hi
                mma16816(acc[i][j], ahi[i], blo[j]);   // hi*lo
                mma16816(acc[i][j], alo[i], bhi[j]);   // lo*hi
            }
        __syncthreads();
    }

    // epilogue
    const int realEnd = g_poff[e] + g_cnt[e];
#pragma unroll
    for (int i = 0; i < 2; i++) {
#pragma unroll
        for (int hh = 0; hh < 2; hh++) {
            int r = row0 + wm * 32 + i * 16 + (lane >> 2) + hh * 8;
            if (r >= realEnd) continue;                 // skip pad rows
            float* drow;
            float scale = 1.f;
            if (SECOND) {
                int n = g_perm[r];
                scale = g_prob[n];
                drow = Dout + (size_t)n * LDB;
            } else {
                drow = Dout + (size_t)r * LDB;
            }
#pragma unroll
            for (int j = 0; j < 8; j++) {
                int lc = wn * 64 + j * 8 + (lane & 3) * 2;
                int cc = blockIdx.x * kBN + lc;
                float v0 = acc[i][j][hh * 2 + 0] + biasE[lc];
                float v1 = acc[i][j][hh * 2 + 1] + biasE[lc + 1];
                if (!SECOND) { v0 = geluf(v0); v1 = geluf(v1); }
                else         { v0 *= scale;  v1 *= scale; }
                drow[cc]     = v0;
                drow[cc + 1] = v1;
            }
        }
    }
}

// ---------------- launch ----------------
extern "C" void kernel_launch(void* const* d_in, const int* in_sizes, int n_in,
                              void* d_out, int out_size) {
    const float* x  = (const float*)d_in[0];
    const float* Wr = (const float*)d_in[1];
    const float* br = (const float*)d_in[2];
    const float* W1 = (const float*)d_in[3];
    const float* b1 = (const float*)d_in[4];
    const float* W2 = (const float*)d_in[5];
    const float* b2 = (const float*)d_in[6];
    float* out = (float*)d_out;
    (void)n_in;

    reset_kernel<<<1, 32>>>();
    router_kernel<<<kN / 8, 256>>>(x, Wr, br);
    float* auxp = (out_size > kN * kC) ? out + (size_t)kN * kC : nullptr;
    offsets_kernel<<<1, 1>>>(auxp);
    gather_kernel<<<kN / 8, 256>>>(x);

    // GEMM1: h = gelu(xg @ W1[e] + b1[e])   [R,1024] x [1024,4096]
    moe_gemm_kernel<kC, kC, kH, false>
        <<<dim3(kH / kBN, kNRT), 256>>>(W1, b1, nullptr);
    // GEMM2: out[n] = prob * (h @ W2[e] + b2[e])   [R,4096] x [4096,1024]
    moe_gemm_kernel<kH, kH, kC, true>
        <<<dim3(kC / kBN, kNRT), 256>>>(W2, b2, out);
}

// round 7
// speedup vs baseline: 2.1298x; 2.1298x over previous
#include <cuda_runtime.h>
#include <cuda_bf16.h>
#include <cstdint>
#include <cstddef>

// ---------------- problem constants ----------------
constexpr int kC  = 1024;
constexpr int kE  = 8;
constexpr int kH  = 4096;
constexpr int kN  = 8192;
constexpr int kBM = 128;               // CTA M tile
constexpr int kBN = 128;               // CTA N tile
constexpr int kRMax = kN + kE * kBM;   // 9216 padded rows
constexpr int kNRT  = kRMax / kBM;     // 72 row tiles
constexpr int kRegB  = kBM * 48;       // 6144 B per region (128 rows x 48B stride)
constexpr int kStageB = 4 * kRegB;     // Ahi|Alo|Bhi|Blo = 24576 B
constexpr int kDynSmem = 2 * kStageB;  // 49152 B = 48KB (no opt-in needed)

// ---------------- device scratch: EXACT round-1 memory profile (189MB) -------
__device__ float g_xg[(size_t)kRMax * kC];        // gathered tokens fp32
__device__ float g_h [(size_t)kRMax * kH];        // hidden activations fp32
__device__ float g_prob[kN];
__device__ int   g_idx[kN];
__device__ int   g_perm[kRMax];
__device__ int   g_cnt[kE];
__device__ int   g_cur[kE];
__device__ int   g_poff[kE + 1];

// ---------------- helpers ----------------
__device__ __forceinline__ uint32_t smem_u32(const void* p) {
    uint32_t a;
    asm("{ .reg .u64 t; cvta.to.shared.u64 t, %1; cvt.u32.u64 %0, t; }" : "=r"(a) : "l"(p));
    return a;
}

#define LDSM4(r, a) \
    asm volatile("ldmatrix.sync.aligned.m8n8.x4.shared.b16 {%0,%1,%2,%3}, [%4];" \
                 : "=r"((r)[0]), "=r"((r)[1]), "=r"((r)[2]), "=r"((r)[3]) : "r"(a))

__device__ __forceinline__ void mma16816(float* c, const uint32_t* a, const uint32_t* b) {
    asm volatile(
        "mma.sync.aligned.m16n8k16.row.col.f32.bf16.bf16.f32 "
        "{%0,%1,%2,%3}, {%4,%5,%6,%7}, {%8,%9}, {%0,%1,%2,%3};\n"
        : "+f"(c[0]), "+f"(c[1]), "+f"(c[2]), "+f"(c[3])
        : "r"(a[0]), "r"(a[1]), "r"(a[2]), "r"(a[3]), "r"(b[0]), "r"(b[1]));
}

__device__ __forceinline__ float geluf(float v) {
    return 0.5f * v * (1.0f + erff(v * 0.70710678118654752f));
}
__device__ __forceinline__ void split_pack(float v0, float v1, uint32_t& hp, uint32_t& lp) {
    __nv_bfloat16 h0 = __float2bfloat16(v0);
    __nv_bfloat16 h1 = __float2bfloat16(v1);
    __nv_bfloat16 l0 = __float2bfloat16(v0 - __bfloat162float(h0));
    __nv_bfloat16 l1 = __float2bfloat16(v1 - __bfloat162float(h1));
    hp = (uint32_t)__bfloat16_as_ushort(h0) | ((uint32_t)__bfloat16_as_ushort(h1) << 16);
    lp = (uint32_t)__bfloat16_as_ushort(l0) | ((uint32_t)__bfloat16_as_ushort(l1) << 16);
}

// ---------------- small kernels (round-1 verbatim) ----------------
__global__ void reset_kernel() {
    int t = threadIdx.x;
    if (t < kE) { g_cnt[t] = 0; g_cur[t] = 0; }
}

__global__ void router_kernel(const float* __restrict__ x,
                              const float* __restrict__ Wr,
                              const float* __restrict__ br) {
    int tok  = (blockIdx.x * blockDim.x + threadIdx.x) >> 5;
    int lane = threadIdx.x & 31;
    if (tok >= kN) return;
    const float* xr = x + (size_t)tok * kC;
    float acc[kE];
#pragma unroll
    for (int e = 0; e < kE; e++) acc[e] = 0.f;
    for (int c = lane; c < kC; c += 32) {
        float xv = xr[c];
        const float4* w = (const float4*)(Wr + (size_t)c * kE);
        float4 w0 = w[0], w1 = w[1];
        acc[0] += xv * w0.x; acc[1] += xv * w0.y; acc[2] += xv * w0.z; acc[3] += xv * w0.w;
        acc[4] += xv * w1.x; acc[5] += xv * w1.y; acc[6] += xv * w1.z; acc[7] += xv * w1.w;
    }
#pragma unroll
    for (int e = 0; e < kE; e++)
        for (int o = 16; o > 0; o >>= 1)
            acc[e] += __shfl_xor_sync(0xffffffffu, acc[e], o);
    if (lane == 0) {
        float m = -1e30f; int bi = 0;
#pragma unroll
        for (int e = 0; e < kE; e++) {
            acc[e] += br[e];
            if (acc[e] > m) { m = acc[e]; bi = e; }
        }
        float s = 0.f;
#pragma unroll
        for (int e = 0; e < kE; e++) s += expf(acc[e] - m);
        g_prob[tok] = 1.f / s;
        g_idx[tok]  = bi;
        atomicAdd(&g_cnt[bi], 1);
    }
}

__global__ void offsets_kernel(float* aux_out) {
    if (threadIdx.x == 0) {
        int p = 0; float s = 0.f;
#pragma unroll
        for (int e = 0; e < kE; e++) {
            g_poff[e] = p;
            int c = g_cnt[e];
            p += (c + kBM - 1) / kBM * kBM;
            float f = (float)c / (float)kN;
            float d = f - (1.0f / (float)kE);
            s += d * d;
        }
        g_poff[kE] = p;
        if (aux_out) *aux_out = s / (float)kE;
    }
}

__global__ void gather_kernel(const float* __restrict__ x) {
    int tok  = (blockIdx.x * blockDim.x + threadIdx.x) >> 5;
    int lane = threadIdx.x & 31;
    if (tok >= kN) return;
    int e = g_idx[tok];
    int pos = 0;
    if (lane == 0) pos = g_poff[e] + atomicAdd(&g_cur[e], 1);
    pos = __shfl_sync(0xffffffffu, pos, 0);
    if (lane == 0) g_perm[pos] = tok;
    const float4* src = (const float4*)(x + (size_t)tok * kC);
    float4* dst = (float4*)(g_xg + (size_t)pos * kC);
#pragma unroll
    for (int i = lane; i < kC / 4; i += 32) dst[i] = src[i];
}

// ---------------- grouped GEMM: fp32 sources, in-kernel hi/lo split ----------
// SECOND=false: g_h = gelu(g_xg @ W1[e] + b1)
// SECOND=true : out[perm[r]] = prob * (g_h @ W2[e] + b2)
template <bool SECOND>
__global__ __launch_bounds__(256)
void moe_mma(const float* __restrict__ Wsrc, const float* __restrict__ bias,
             float* __restrict__ OutP) {
    constexpr int KDIM = SECOND ? kH : kC;
    constexpr int ND   = SECOND ? kC : kH;
    constexpr int KB   = KDIM / 16;

    extern __shared__ char smc[];
    const uint32_t sb = smem_u32(smc);

    const int rt = blockIdx.y, bx = blockIdx.x;
    const int row0 = rt * kBM;
    if (row0 >= g_poff[kE]) return;
    int e = 0;
    while (e < kE - 1 && row0 >= g_poff[e + 1]) e++;

    const float* A = (SECOND ? g_h : g_xg) + (size_t)row0 * KDIM;
    const float* B = Wsrc + (size_t)e * KDIM * ND + (size_t)bx * kBN;

    const int tid  = threadIdx.x;
    const int warp = tid >> 5;
    const int lane = tid & 31;
    const int wm   = warp & 3;
    const int wn   = warp >> 2;

    // fill assignment
    const int arow = tid >> 1, ah = tid & 1;           // A: 128 rows x 2 halves
    const float* Aload = A + (size_t)arow * KDIM + ah * 8;
    const int bn = tid & 127, bkp = tid >> 7;          // B: 128 n-cols x 2 k-octets
    const float* Bload = B + (size_t)bkp * 8 * ND + bn;

    float ra[8], rb[8], ra2[8], rb2[8];
    auto load_regs = [&](int kb, float* a, float* b) {
        float4 a0 = *(const float4*)(Aload + kb * 16);
        float4 a1 = *(const float4*)(Aload + kb * 16 + 4);
        a[0]=a0.x; a[1]=a0.y; a[2]=a0.z; a[3]=a0.w;
        a[4]=a1.x; a[5]=a1.y; a[6]=a1.z; a[7]=a1.w;
#pragma unroll
        for (int i = 0; i < 8; i++)
            b[i] = Bload[(size_t)(kb * 16 + i) * ND];
    };
    auto store_stage = [&](int s, const float* a, const float* b) {
        char* base = smc + (size_t)s * kStageB;
        uint32_t h[4], l[4];
#pragma unroll
        for (int i = 0; i < 4; i++) split_pack(a[2*i], a[2*i+1], h[i], l[i]);
        *(uint4*)(base + (size_t)arow * 48 + ah * 16) = make_uint4(h[0], h[1], h[2], h[3]);
        *(uint4*)(base + kRegB + (size_t)arow * 48 + ah * 16) = make_uint4(l[0], l[1], l[2], l[3]);
#pragma unroll
        for (int i = 0; i < 4; i++) {
            uint32_t hp, lp;
            split_pack(b[2*i], b[2*i+1], hp, lp);
            *(uint32_t*)(base + 2*kRegB + (size_t)bn * 48 + bkp * 16 + i * 4) = hp;
            *(uint32_t*)(base + 3*kRegB + (size_t)bn * 48 + bkp * 16 + i * 4) = lp;
        }
    };

    // ldmatrix byte offsets within one region (row stride 48B)
    uint32_t offA[2], offB[4];
#pragma unroll
    for (int i = 0; i < 2; i++) {
        uint32_t row = wm * 32 + i * 16 + ((lane >> 3) & 1) * 8 + (lane & 7);
        offA[i] = row * 48 + (lane >> 4) * 16;
    }
#pragma unroll
    for (int jp = 0; jp < 4; jp++) {
        uint32_t row = wn * 64 + jp * 16 + (lane >> 4) * 8 + (lane & 7);
        offB[jp] = row * 48 + ((lane >> 3) & 1) * 16;
    }

    float acc[2][8][4];
#pragma unroll
    for (int i = 0; i < 2; i++)
#pragma unroll
        for (int j = 0; j < 8; j++)
#pragma unroll
            for (int q = 0; q < 4; q++) acc[i][j][q] = 0.f;

    load_regs(0, ra, rb);
    store_stage(0, ra, rb);
    __syncthreads();
    load_regs(1, ra, rb);

    for (int kb = 0; kb < KB; kb++) {
        const int s = kb & 1;
        if (kb + 1 < KB) store_stage(s ^ 1, ra, rb);
        if (kb + 2 < KB) load_regs(kb + 2, ra2, rb2);

        const uint32_t st = sb + (uint32_t)s * kStageB;
        uint32_t ahi[2][4], alo[2][4], bhi[4][4], blo[4][4];
#pragma unroll
        for (int i = 0; i < 2; i++) {
            LDSM4(ahi[i], st + offA[i]);
            LDSM4(alo[i], st + (uint32_t)kRegB + offA[i]);
        }
#pragma unroll
        for (int jp = 0; jp < 4; jp++) {
            LDSM4(bhi[jp], st + 2u * kRegB + offB[jp]);
            LDSM4(blo[jp], st + 3u * kRegB + offB[jp]);
        }
#pragma unroll
        for (int i = 0; i < 2; i++)
#pragma unroll
            for (int j = 0; j < 8; j++) {
                int jp = j >> 1, s2 = (j & 1) * 2;
                mma16816(acc[i][j], ahi[i], &bhi[jp][s2]);
                mma16816(acc[i][j], ahi[i], &blo[jp][s2]);
                mma16816(acc[i][j], alo[i], &bhi[jp][s2]);
            }
#pragma unroll
        for (int q = 0; q < 8; q++) { ra[q] = ra2[q]; rb[q] = rb2[q]; }
        __syncthreads();
    }

    // ---------------- epilogue (round-1 semantics) ----------------
    const int realEnd = g_poff[e] + g_cnt[e];
    const float* biasE = bias + (size_t)e * ND + (size_t)bx * kBN;
    const int r0 = wm * 32 + (lane >> 2);
    const int c0 = (lane & 3) * 2;

#pragma unroll
    for (int i = 0; i < 2; i++)
#pragma unroll
        for (int hh = 0; hh < 2; hh++) {
            int r = row0 + r0 + i * 16 + hh * 8;
            if (r >= realEnd) continue;
            if (!SECOND) {
                float* drow = g_h + (size_t)r * kH + (size_t)bx * kBN;
#pragma unroll
                for (int j = 0; j < 8; j++) {
                    int col = wn * 64 + j * 8 + c0;
                    float2 v;
                    v.x = geluf(acc[i][j][hh * 2 + 0] + biasE[col]);
                    v.y = geluf(acc[i][j][hh * 2 + 1] + biasE[col + 1]);
                    *(float2*)(drow + col) = v;
                }
            } else {
                int n = g_perm[r];
                float sc = g_prob[n];
                float* orow = OutP + (size_t)n * kC + (size_t)bx * kBN;
#pragma unroll
                for (int j = 0; j < 8; j++) {
                    int col = wn * 64 + j * 8 + c0;
                    float2 v;
                    v.x = (acc[i][j][hh * 2 + 0] + biasE[col]) * sc;
                    v.y = (acc[i][j][hh * 2 + 1] + biasE[col + 1]) * sc;
                    *(float2*)(orow + col) = v;
                }
            }
        }
}

// ---------------- launch ----------------
extern "C" void kernel_launch(void* const* d_in, const int* in_sizes, int n_in,
                              void* d_out, int out_size) {
    const float* x  = (const float*)d_in[0];
    const float* Wr = (const float*)d_in[1];
    const float* br = (const float*)d_in[2];
    const float* W1 = (const float*)d_in[3];
    const float* b1 = (const float*)d_in[4];
    const float* W2 = (const float*)d_in[5];
    const float* b2 = (const float*)d_in[6];
    float* out = (float*)d_out;
    (void)n_in;

    reset_kernel<<<1, 32>>>();
    router_kernel<<<kN / 8, 256>>>(x, Wr, br);
    float* auxp = (out_size > kN * kC) ? out + (size_t)kN * kC : nullptr;
    offsets_kernel<<<1, 1>>>(auxp);
    gather_kernel<<<kN / 8, 256>>>(x);

    moe_mma<false><<<dim3(kH / kBN, kNRT), 256, kDynSmem>>>(W1, b1, nullptr);
    moe_mma<true ><<<dim3(kC / kBN, kNRT), 256, kDynSmem>>>(W2, b2, out);
}